// round 13
// baseline (speedup 1.0000x reference)
#include <cuda_runtime.h>
#include <cuda_fp16.h>
#include <cuda_bf16.h>
#include <cstdint>

#define VOCAB   100000
#define N_TOK   819200
#define BATCH   4096
#define HID     256
#define BN_EPS  1e-5f
#define NBLK    128        // fused grid size (4 x 32); single wave (<=148 SMs)

// ---------------- device scratch (no allocations allowed) ----------------
__device__ __align__(16) __half g_emb_h[(size_t)VOCAB * HID];  // 51.2 MB fp16 table
__device__ __align__(16) float g_segsum[BATCH * HID];          // 4 MB
__device__ __align__(16) float g_counts[BATCH];
__device__ __align__(16) float g_sums[HID];
__device__ __align__(16) float g_sumsq[HID];
__device__ __align__(16) float g_logit[BATCH];
__device__ float g_loss;
__device__ int   g_nz;     // nonzero odd words => int32 ids
__device__ int   g_done;   // ticket over the 32 row-group finalizers
__device__ int   g_cnt1;
__device__ volatile int g_flag1;
__device__ int   g_cnt_row[32];          // per-by arrival counters

// ------- prep half-plane: fp32->fp16 for dims [half*128, half*128+128) ----
// 6250 convert blocks; half==0 additionally carries init blocks (1026 more).
__global__ void __launch_bounds__(256)
k_prep_half(const float* __restrict__ emb, const int* __restrict__ tok, int half) {
    const int bid = blockIdx.x, tid = threadIdx.x;
    if (bid < 6250) {
        const int t = bid * 256 + tid;          // 1.6M tasks, 8 elems each
        const int row = t >> 4;
        const int off = (t & 15) * 8;
        const size_t base = (size_t)row * HID + half * 128 + off;
        const float4* src = (const float4*)(emb + base);
        float4 v0 = __ldcs(src);
        float4 v1 = __ldcs(src + 1);
        uint4 pack;
        __half2 h;
        h = __floats2half2_rn(v0.x, v0.y); pack.x = *(uint32_t*)&h;
        h = __floats2half2_rn(v0.z, v0.w); pack.y = *(uint32_t*)&h;
        h = __floats2half2_rn(v1.x, v1.y); pack.z = *(uint32_t*)&h;
        h = __floats2half2_rn(v1.z, v1.w); pack.w = *(uint32_t*)&h;
        *(uint4*)(g_emb_h + base) = pack;
        return;
    }
    // init blocks (only launched for half==0)
    const int ib = bid - 6250;
    if (ib < 1024) {
        *(float4*)&g_segsum[ib * 1024 + tid * 4] = make_float4(0.f, 0.f, 0.f, 0.f);
    } else if (ib == 1024) {
        float4 z = make_float4(0.f, 0.f, 0.f, 0.f);
        #pragma unroll
        for (int i = 0; i < 4; i++) {
            *(float4*)&g_counts[tid * 16 + i * 4] = z;
            *(float4*)&g_logit[tid * 16 + i * 4] = z;
        }
        g_sums[tid] = 0.f;
        g_sumsq[tid] = 0.f;
        if (tid < 32) g_cnt_row[tid] = 0;
        if (tid == 0) { g_loss = 0.f; g_done = 0; g_cnt1 = 0; g_flag1 = 0; }
    } else if (ib == 1025 && tid < 64) {
        if (tok[2 * tid + 1] != 0) atomicOr(&g_nz, 1);
    }
}

// ------- gather pass: accumulate dims [pass*128, pass*128+128) -------------
#define TOK_PER_WARP 64
#define GATHER_WARPS 8

__device__ __forceinline__ void flush_run4(int seg, const float* a, int runlen,
                                           int lane, size_t lane_off, int pass) {
    float* dst = g_segsum + (size_t)seg * HID + lane_off;
    asm volatile("red.global.add.v4.f32 [%0], {%1,%2,%3,%4};"
                 :: "l"(dst), "f"(a[0]), "f"(a[1]), "f"(a[2]), "f"(a[3]) : "memory");
    if (pass == 0 && lane == 0) atomicAdd(&g_counts[seg], (float)runlen);
}

__global__ void __launch_bounds__(GATHER_WARPS * 32)
k_gather(const int* __restrict__ tok, const int* __restrict__ seg, int pass) {
    const int stride = g_nz ? 1 : 2;
    const int lane = threadIdx.x & 31;
    const int warp_id = blockIdx.x * GATHER_WARPS + (threadIdx.x >> 5);
    const int t0 = warp_id * TOK_PER_WARP;

    int idp[2], sgp[2];
    idp[0] = tok[(size_t)(t0 + lane) * stride];
    idp[1] = tok[(size_t)(t0 + 32 + lane) * stride];
    sgp[0] = seg[(size_t)(t0 + lane) * stride];
    sgp[1] = seg[(size_t)(t0 + 32 + lane) * stride];

    float a[4] = {0.f, 0.f, 0.f, 0.f};
    int cur = __shfl_sync(0xFFFFFFFFu, sgp[0], 0);
    int runlen = 0;

    const size_t lane_off = (size_t)pass * 128 + lane * 4;

    #pragma unroll
    for (int hf = 0; hf < 2; ++hf) {
        #pragma unroll 8
        for (int i = 0; i < 32; ++i) {
            int s  = __shfl_sync(0xFFFFFFFFu, sgp[hf], i);
            int id = __shfl_sync(0xFFFFFFFFu, idp[hf], i);
            if (s != cur) {
                flush_run4(cur, a, runlen, lane, lane_off, pass);
                a[0] = a[1] = a[2] = a[3] = 0.f;
                runlen = 0;
                cur = s;
            }
            uint2 v = *(const uint2*)(g_emb_h + (size_t)id * HID + lane_off);
            const __half2* hp = (const __half2*)&v;
            float2 f;
            f = __half22float2(hp[0]); a[0] += f.x; a[1] += f.y;
            f = __half22float2(hp[1]); a[2] += f.x; a[3] += f.y;
            ++runlen;
        }
    }
    flush_run4(cur, a, runlen, lane, lane_off, pass);
}

// ---------------- fused GEMM + BN + ReLU + W2 + BCE (persistent) ----------
#define BM 128
#define BN 64
#define APAD 264   // halves per row; 528B pitch => ldmatrix conflict-free
#define SA_HALVES (BM * APAD)
#define SB_HALVES (BN * APAD)
#define DYN_SMEM ((SA_HALVES + SB_HALVES) * 2)

__device__ __forceinline__ void ldsm4(uint32_t& r0, uint32_t& r1, uint32_t& r2,
                                      uint32_t& r3, const void* p) {
    uint32_t addr = (uint32_t)__cvta_generic_to_shared(p);
    asm volatile("ldmatrix.sync.aligned.m8n8.x4.shared.b16 {%0,%1,%2,%3}, [%4];"
                 : "=r"(r0), "=r"(r1), "=r"(r2), "=r"(r3) : "r"(addr));
}

__device__ __forceinline__ void mma16816h(float* c, uint32_t a0, uint32_t a1,
                                          uint32_t a2, uint32_t a3,
                                          uint32_t b0, uint32_t b1) {
    asm volatile(
        "mma.sync.aligned.m16n8k16.row.col.f32.f16.f16.f32 "
        "{%0,%1,%2,%3}, {%4,%5,%6,%7}, {%8,%9}, {%0,%1,%2,%3};"
        : "+f"(c[0]), "+f"(c[1]), "+f"(c[2]), "+f"(c[3])
        : "r"(a0), "r"(a1), "r"(a2), "r"(a3), "r"(b0), "r"(b1));
}

// R7-proven single-wave full grid barrier
__device__ __forceinline__ void grid_sync(int tid, int* cnt, volatile int* flag) {
    __syncthreads();
    if (tid == 0) {
        __threadfence();
        if (atomicAdd(cnt, 1) == NBLK - 1) {
            *flag = 1;
        } else {
            while (*flag == 0) __nanosleep(64);
        }
    }
    __syncthreads();
}

__device__ __forceinline__ uint4 pack8(const float* f) {
    uint4 o;
    __half2 h;
    h = __floats2half2_rn(f[0], f[1]); o.x = *(uint32_t*)&h;
    h = __floats2half2_rn(f[2], f[3]); o.y = *(uint32_t*)&h;
    h = __floats2half2_rn(f[4], f[5]); o.z = *(uint32_t*)&h;
    h = __floats2half2_rn(f[6], f[7]); o.w = *(uint32_t*)&h;
    return o;
}

__global__ void __launch_bounds__(256)
k_fused(const float* __restrict__ W1, const float* __restrict__ b1,
        const float* __restrict__ gamma, const float* __restrict__ beta,
        const float* __restrict__ W2, const float* __restrict__ b2,
        const float* __restrict__ labels, float* __restrict__ out) {
    extern __shared__ __align__(16) char dynsmem[];
    __half (*sA)[APAD] = (__half (*)[APAD])dynsmem;
    __half (*sB)[APAD] = (__half (*)[APAD])(dynsmem + SA_HALVES * 2);

    __shared__ float s_invc[BM];
    __shared__ float s_stat[2][BN];
    __shared__ float s_sc[BN], s_sh[BN], s_w2[BN];
    __shared__ int s_last;
    __shared__ float s_lred[4];

    const int tid = threadIdx.x;
    const int m0 = blockIdx.y * BM;
    const int n0 = blockIdx.x * BN;

    if (tid < BN) { s_stat[0][tid] = 0.f; s_stat[1][tid] = 0.f; }
    if (tid < BM) s_invc[tid] = 1.f / fmaxf(g_counts[m0 + tid], 1.f);
    __syncthreads();

    #pragma unroll
    for (int i = 0; i < 16; i++) {
        const int task = i * 256 + tid;
        const int row = task >> 5, c8 = (task & 31) * 8;
        float f[8];
        *(float4*)&f[0] = *(const float4*)&g_segsum[(size_t)(m0 + row) * HID + c8];
        *(float4*)&f[4] = *(const float4*)&g_segsum[(size_t)(m0 + row) * HID + c8 + 4];
        const float ic = s_invc[row];
        #pragma unroll
        for (int j = 0; j < 8; j++) f[j] *= ic;
        *(uint4*)&sA[row][c8] = pack8(f);
    }
    #pragma unroll
    for (int i = 0; i < 8; i++) {
        const int task = i * 256 + tid;
        const int row = task >> 5, c8 = (task & 31) * 8;
        float f[8];
        *(float4*)&f[0] = *(const float4*)&W1[(size_t)(n0 + row) * HID + c8];
        *(float4*)&f[4] = *(const float4*)&W1[(size_t)(n0 + row) * HID + c8 + 4];
        *(uint4*)&sB[row][c8] = pack8(f);
    }
    __syncthreads();

    const int warp = tid >> 5, lane = tid & 31;
    const int wm0 = (warp >> 1) * 32;
    const int wn0 = (warp & 1) * 32;
    const int q = lane >> 3, r = lane & 7;

    float acc[2][4][4];
    #pragma unroll
    for (int i = 0; i < 2; i++)
        #pragma unroll
        for (int j = 0; j < 4; j++)
            #pragma unroll
            for (int k = 0; k < 4; k++) acc[i][j][k] = 0.f;

    #pragma unroll
    for (int kk = 0; kk < HID; kk += 16) {
        uint32_t ah[2][4], bh[2][4];
        #pragma unroll
        for (int mt = 0; mt < 2; mt++) {
            const int row = wm0 + mt * 16 + (q & 1) * 8 + r;
            const int col = kk + (q >> 1) * 8;
            ldsm4(ah[mt][0], ah[mt][1], ah[mt][2], ah[mt][3], &sA[row][col]);
        }
        #pragma unroll
        for (int p = 0; p < 2; p++) {
            const int row = wn0 + p * 16 + (q >> 1) * 8 + r;
            const int col = kk + (q & 1) * 8;
            ldsm4(bh[p][0], bh[p][1], bh[p][2], bh[p][3], &sB[row][col]);
        }
        #pragma unroll
        for (int mt = 0; mt < 2; mt++)
            #pragma unroll
            for (int nt = 0; nt < 4; nt++)
                mma16816h(acc[mt][nt], ah[mt][0], ah[mt][1], ah[mt][2], ah[mt][3],
                          bh[nt >> 1][(nt & 1) * 2], bh[nt >> 1][(nt & 1) * 2 + 1]);
    }

    float pre_g = 0.f, pre_b = 0.f, pre_w = 0.f;
    if (tid < BN) {
        pre_g = gamma[n0 + tid];
        pre_b = beta[n0 + tid];
        pre_w = W2[n0 + tid];
    }
    const float b2v = b2[0];

    #pragma unroll
    for (int nt = 0; nt < 4; nt++) {
        const int col = n0 + wn0 + nt * 8 + (lane & 3) * 2;
        const float bx = b1[col], by = b1[col + 1];
        float sx = 0.f, sy = 0.f, qx = 0.f, qy = 0.f;
        #pragma unroll
        for (int mt = 0; mt < 2; mt++) {
            acc[mt][nt][0] += bx; acc[mt][nt][1] += by;
            acc[mt][nt][2] += bx; acc[mt][nt][3] += by;
            sx += acc[mt][nt][0] + acc[mt][nt][2];
            sy += acc[mt][nt][1] + acc[mt][nt][3];
            qx = fmaf(acc[mt][nt][0], acc[mt][nt][0], qx);
            qx = fmaf(acc[mt][nt][2], acc[mt][nt][2], qx);
            qy = fmaf(acc[mt][nt][1], acc[mt][nt][1], qy);
            qy = fmaf(acc[mt][nt][3], acc[mt][nt][3], qy);
        }
        #pragma unroll
        for (int off = 16; off >= 4; off >>= 1) {
            sx += __shfl_down_sync(0xFFFFFFFFu, sx, off);
            sy += __shfl_down_sync(0xFFFFFFFFu, sy, off);
            qx += __shfl_down_sync(0xFFFFFFFFu, qx, off);
            qy += __shfl_down_sync(0xFFFFFFFFu, qy, off);
        }
        if (lane < 4) {
            const int c = wn0 + nt * 8 + lane * 2;
            atomicAdd(&s_stat[0][c], sx);
            atomicAdd(&s_stat[0][c + 1], sy);
            atomicAdd(&s_stat[1][c], qx);
            atomicAdd(&s_stat[1][c + 1], qy);
        }
    }
    __syncthreads();
    if (tid < BN) {
        atomicAdd(&g_sums[n0 + tid], s_stat[0][tid]);
        atomicAdd(&g_sumsq[n0 + tid], s_stat[1][tid]);
    }

    grid_sync(tid, &g_cnt1, &g_flag1);

    if (tid < BN) {
        const int c = n0 + tid;
        float mean = __ldcg(&g_sums[c]) * (1.f / BATCH);
        float var = fmaxf(__ldcg(&g_sumsq[c]) * (1.f / BATCH) - mean * mean, 0.f);
        float rstd = rsqrtf(var + BN_EPS);
        float sc = pre_g * rstd;
        s_sc[tid] = sc;
        s_sh[tid] = fmaf(-mean, sc, pre_b);
        s_w2[tid] = pre_w;
    }
    __syncthreads();

    {
        const int cl = wn0 + (lane & 3) * 2;
        float p[2][2];
        p[0][0] = p[0][1] = p[1][0] = p[1][1] = 0.f;
        #pragma unroll
        for (int nt = 0; nt < 4; nt++) {
            const int c0 = cl + nt * 8, c1 = c0 + 1;
            const float sc0 = s_sc[c0], sh0 = s_sh[c0], w20 = s_w2[c0];
            const float sc1 = s_sc[c1], sh1 = s_sh[c1], w21 = s_w2[c1];
            #pragma unroll
            for (int mt = 0; mt < 2; mt++) {
                float x;
                x = fmaxf(fmaf(acc[mt][nt][0], sc0, sh0), 0.f); p[mt][0] = fmaf(x, w20, p[mt][0]);
                x = fmaxf(fmaf(acc[mt][nt][1], sc1, sh1), 0.f); p[mt][0] = fmaf(x, w21, p[mt][0]);
                x = fmaxf(fmaf(acc[mt][nt][2], sc0, sh0), 0.f); p[mt][1] = fmaf(x, w20, p[mt][1]);
                x = fmaxf(fmaf(acc[mt][nt][3], sc1, sh1), 0.f); p[mt][1] = fmaf(x, w21, p[mt][1]);
            }
        }
        #pragma unroll
        for (int off = 2; off >= 1; off >>= 1) {
            #pragma unroll
            for (int mt = 0; mt < 2; mt++) {
                p[mt][0] += __shfl_down_sync(0xFFFFFFFFu, p[mt][0], off);
                p[mt][1] += __shfl_down_sync(0xFFFFFFFFu, p[mt][1], off);
            }
        }
        if ((lane & 3) == 0) {
            const int row0 = m0 + wm0 + (lane >> 2);
            #pragma unroll
            for (int mt = 0; mt < 2; mt++) {
                atomicAdd(&g_logit[row0 + mt * 16], p[mt][0]);
                atomicAdd(&g_logit[row0 + mt * 16 + 8], p[mt][1]);
            }
        }
    }

    __threadfence();
    __syncthreads();
    if (tid == 0) s_last = atomicAdd(&g_cnt_row[blockIdx.y], 1);
    __syncthreads();
    if (s_last != 3) return;

    {
        float l = 0.f;
        if (tid < BM) {
            const int row = m0 + tid;
            float logit = __ldcg(&g_logit[row]) + b2v;
            out[1 + row] = logit;
            float y = labels[row];
            l = fmaxf(logit, 0.f) - logit * y + log1pf(expf(-fabsf(logit)));
        }
        #pragma unroll
        for (int off = 16; off > 0; off >>= 1)
            l += __shfl_down_sync(0xFFFFFFFFu, l, off);
        if (lane == 0 && warp < 4) s_lred[warp] = l;
        __syncthreads();
        if (tid == 0) {
            float L = s_lred[0] + s_lred[1] + s_lred[2] + s_lred[3];
            atomicAdd(&g_loss, L);
            __threadfence();
            if (atomicAdd(&g_done, 1) == 31) {
                out[0] = atomicAdd(&g_loss, 0.f) * (1.f / BATCH);
            }
        }
    }
}

// ---------------- launch: forked-stream overlap of prep half 1 with gather 0
extern "C" void kernel_launch(void* const* d_in, const int* in_sizes, int n_in,
                              void* d_out, int out_size) {
    const int*   tok    = (const int*)d_in[0];
    const int*   seg    = (const int*)d_in[1];
    const float* labels = (const float*)d_in[2];
    const float* emb    = (const float*)d_in[3];
    const float* W1     = (const float*)d_in[4];
    const float* b1     = (const float*)d_in[5];
    const float* gamma  = (const float*)d_in[6];
    const float* beta   = (const float*)d_in[7];
    const float* W2     = (const float*)d_in[8];
    const float* b2     = (const float*)d_in[9];
    float* out = (float*)d_out;

    static cudaStream_t s1 = nullptr;
    static cudaEvent_t ev_fork = nullptr, ev_join = nullptr;
    if (s1 == nullptr) {   // first call is the uncaptured correctness run
        cudaStreamCreateWithFlags(&s1, cudaStreamNonBlocking);
        cudaEventCreateWithFlags(&ev_fork, cudaEventDisableTiming);
        cudaEventCreateWithFlags(&ev_join, cudaEventDisableTiming);
        cudaFuncSetAttribute(k_fused, cudaFuncAttributeMaxDynamicSharedMemorySize,
                             DYN_SMEM);
    }

    // prep half 0 (+ all zero-init + dtype detect)
    k_prep_half<<<6250 + 1026, 256>>>(emb, tok, 0);

    // fork: prep half 1 on s1, concurrent with gather pass 0
    cudaEventRecord(ev_fork, 0);
    cudaStreamWaitEvent(s1, ev_fork, 0);
    k_prep_half<<<6250, 256, 0, s1>>>(emb, tok, 1);
    cudaEventRecord(ev_join, s1);

    k_gather<<<N_TOK / (TOK_PER_WARP * GATHER_WARPS), GATHER_WARPS * 32>>>(tok, seg, 0);

    // join: pass 1 needs half-1 of the table
    cudaStreamWaitEvent(0, ev_join, 0);
    k_gather<<<N_TOK / (TOK_PER_WARP * GATHER_WARPS), GATHER_WARPS * 32>>>(tok, seg, 1);

    k_fused<<<dim3(HID / BN, BATCH / BM), 256, DYN_SMEM>>>(W1, b1, gamma, beta, W2,
                                                           b2, labels, out);
}

// round 14
// speedup vs baseline: 1.2314x; 1.2314x over previous
#include <cuda_runtime.h>
#include <cuda_fp16.h>
#include <cuda_bf16.h>
#include <cstdint>

#define VOCAB   100000
#define N_TOK   819200
#define BATCH   4096
#define HID     256
#define BN_EPS  1e-5f
#define NBLK    128        // fused grid size (4 x 32); single wave (<=148 SMs)

// ---------------- device scratch (no allocations allowed) ----------------
__device__ __align__(16) __half g_emb_h[(size_t)VOCAB * HID];  // 51.2 MB fp16 table
__device__ __align__(16) float g_segsum[BATCH * HID];          // 4 MB
__device__ __align__(16) float g_counts[BATCH];
__device__ __align__(16) float g_sums[HID];
__device__ __align__(16) float g_sumsq[HID];
__device__ __align__(16) float g_logit[BATCH];
__device__ float g_loss;
__device__ int   g_nz;     // nonzero odd words => int32 ids
__device__ int   g_done;   // ticket over the 32 row-group finalizers
__device__ int   g_cnt1;
__device__ volatile int g_flag1;
__device__ int   g_cnt_row[32];          // per-by arrival counters

// ------- prep half-plane: fp32->fp16 for dims [half*128, half*128+128) ----
// 6250 convert blocks; half==0 additionally carries init blocks (1026 more).
__global__ void __launch_bounds__(256)
k_prep_half(const float* __restrict__ emb, const int* __restrict__ tok, int half) {
    const int bid = blockIdx.x, tid = threadIdx.x;
    if (bid < 6250) {
        const int t = bid * 256 + tid;          // 1.6M tasks, 8 elems each
        const int row = t >> 4;
        const int off = (t & 15) * 8;
        const size_t base = (size_t)row * HID + half * 128 + off;
        const float4* src = (const float4*)(emb + base);
        float4 v0 = __ldcs(src);
        float4 v1 = __ldcs(src + 1);
        uint4 pack;
        __half2 h;
        h = __floats2half2_rn(v0.x, v0.y); pack.x = *(uint32_t*)&h;
        h = __floats2half2_rn(v0.z, v0.w); pack.y = *(uint32_t*)&h;
        h = __floats2half2_rn(v1.x, v1.y); pack.z = *(uint32_t*)&h;
        h = __floats2half2_rn(v1.z, v1.w); pack.w = *(uint32_t*)&h;
        *(uint4*)(g_emb_h + base) = pack;
        return;
    }
    // init blocks (only launched for half==0)
    const int ib = bid - 6250;
    if (ib < 1024) {
        *(float4*)&g_segsum[ib * 1024 + tid * 4] = make_float4(0.f, 0.f, 0.f, 0.f);
    } else if (ib == 1024) {
        float4 z = make_float4(0.f, 0.f, 0.f, 0.f);
        #pragma unroll
        for (int i = 0; i < 4; i++) {
            *(float4*)&g_counts[tid * 16 + i * 4] = z;
            *(float4*)&g_logit[tid * 16 + i * 4] = z;
        }
        g_sums[tid] = 0.f;
        g_sumsq[tid] = 0.f;
        if (tid < 32) g_cnt_row[tid] = 0;
        if (tid == 0) { g_loss = 0.f; g_done = 0; g_cnt1 = 0; g_flag1 = 0; }
    } else if (ib == 1025 && tid < 64) {
        if (tok[2 * tid + 1] != 0) atomicOr(&g_nz, 1);
    }
}

// ------- gather pass: accumulate dims [pass*128, pass*128+128) -------------
// MLP fix vs R13: 16 unconditional LDG.64 batched into registers BEFORE the
// flush loop (128B in flight per warp = same as the cap-achieving full gather).
#define TOK_PER_WARP 64
#define GATHER_WARPS 8

__device__ __forceinline__ void flush_run4(int seg, const float* a, int runlen,
                                           int lane, size_t lane_off, int pass) {
    float* dst = g_segsum + (size_t)seg * HID + lane_off;
    asm volatile("red.global.add.v4.f32 [%0], {%1,%2,%3,%4};"
                 :: "l"(dst), "f"(a[0]), "f"(a[1]), "f"(a[2]), "f"(a[3]) : "memory");
    if (pass == 0 && lane == 0) atomicAdd(&g_counts[seg], (float)runlen);
}

__global__ void __launch_bounds__(GATHER_WARPS * 32)
k_gather(const int* __restrict__ tok, const int* __restrict__ seg, int pass) {
    const int stride = g_nz ? 1 : 2;
    const int lane = threadIdx.x & 31;
    const int warp_id = blockIdx.x * GATHER_WARPS + (threadIdx.x >> 5);
    const int t0 = warp_id * TOK_PER_WARP;

    int idp[2], sgp[2];
    idp[0] = tok[(size_t)(t0 + lane) * stride];
    idp[1] = tok[(size_t)(t0 + 32 + lane) * stride];
    sgp[0] = seg[(size_t)(t0 + lane) * stride];
    sgp[1] = seg[(size_t)(t0 + 32 + lane) * stride];

    float a[4] = {0.f, 0.f, 0.f, 0.f};
    int cur = __shfl_sync(0xFFFFFFFFu, sgp[0], 0);
    int runlen = 0;

    const size_t lane_off = (size_t)pass * 128 + lane * 4;
    const __half* tbl = g_emb_h + lane_off;

    #pragma unroll
    for (int hf = 0; hf < 2; ++hf) {
        #pragma unroll
        for (int b = 0; b < 2; ++b) {
            // batch-load 16 tokens (independent, before any flush clobber)
            uint2 v[16];
            #pragma unroll
            for (int i = 0; i < 16; ++i) {
                int id = __shfl_sync(0xFFFFFFFFu, idp[hf], b * 16 + i);
                v[i] = *(const uint2*)(tbl + (size_t)id * HID);
            }
            // boundary/accumulate loop
            #pragma unroll
            for (int i = 0; i < 16; ++i) {
                int s = __shfl_sync(0xFFFFFFFFu, sgp[hf], b * 16 + i);
                if (s != cur) {
                    flush_run4(cur, a, runlen, lane, lane_off, pass);
                    a[0] = a[1] = a[2] = a[3] = 0.f;
                    runlen = 0;
                    cur = s;
                }
                const __half2* hp = (const __half2*)&v[i];
                float2 f;
                f = __half22float2(hp[0]); a[0] += f.x; a[1] += f.y;
                f = __half22float2(hp[1]); a[2] += f.x; a[3] += f.y;
                ++runlen;
            }
        }
    }
    flush_run4(cur, a, runlen, lane, lane_off, pass);
}

// ---------------- fused GEMM + BN + ReLU + W2 + BCE (persistent) ----------
#define BM 128
#define BN 64
#define APAD 264   // halves per row; 528B pitch => ldmatrix conflict-free
#define SA_HALVES (BM * APAD)
#define SB_HALVES (BN * APAD)
#define DYN_SMEM ((SA_HALVES + SB_HALVES) * 2)

__device__ __forceinline__ void ldsm4(uint32_t& r0, uint32_t& r1, uint32_t& r2,
                                      uint32_t& r3, const void* p) {
    uint32_t addr = (uint32_t)__cvta_generic_to_shared(p);
    asm volatile("ldmatrix.sync.aligned.m8n8.x4.shared.b16 {%0,%1,%2,%3}, [%4];"
                 : "=r"(r0), "=r"(r1), "=r"(r2), "=r"(r3) : "r"(addr));
}

__device__ __forceinline__ void mma16816h(float* c, uint32_t a0, uint32_t a1,
                                          uint32_t a2, uint32_t a3,
                                          uint32_t b0, uint32_t b1) {
    asm volatile(
        "mma.sync.aligned.m16n8k16.row.col.f32.f16.f16.f32 "
        "{%0,%1,%2,%3}, {%4,%5,%6,%7}, {%8,%9}, {%0,%1,%2,%3};"
        : "+f"(c[0]), "+f"(c[1]), "+f"(c[2]), "+f"(c[3])
        : "r"(a0), "r"(a1), "r"(a2), "r"(a3), "r"(b0), "r"(b1));
}

// R7-proven single-wave full grid barrier
__device__ __forceinline__ void grid_sync(int tid, int* cnt, volatile int* flag) {
    __syncthreads();
    if (tid == 0) {
        __threadfence();
        if (atomicAdd(cnt, 1) == NBLK - 1) {
            *flag = 1;
        } else {
            while (*flag == 0) __nanosleep(64);
        }
    }
    __syncthreads();
}

__device__ __forceinline__ uint4 pack8(const float* f) {
    uint4 o;
    __half2 h;
    h = __floats2half2_rn(f[0], f[1]); o.x = *(uint32_t*)&h;
    h = __floats2half2_rn(f[2], f[3]); o.y = *(uint32_t*)&h;
    h = __floats2half2_rn(f[4], f[5]); o.z = *(uint32_t*)&h;
    h = __floats2half2_rn(f[6], f[7]); o.w = *(uint32_t*)&h;
    return o;
}

__global__ void __launch_bounds__(256)
k_fused(const float* __restrict__ W1, const float* __restrict__ b1,
        const float* __restrict__ gamma, const float* __restrict__ beta,
        const float* __restrict__ W2, const float* __restrict__ b2,
        const float* __restrict__ labels, float* __restrict__ out) {
    extern __shared__ __align__(16) char dynsmem[];
    __half (*sA)[APAD] = (__half (*)[APAD])dynsmem;
    __half (*sB)[APAD] = (__half (*)[APAD])(dynsmem + SA_HALVES * 2);

    __shared__ float s_invc[BM];
    __shared__ float s_stat[2][BN];
    __shared__ float s_sc[BN], s_sh[BN], s_w2[BN];
    __shared__ int s_last;
    __shared__ float s_lred[4];

    const int tid = threadIdx.x;
    const int m0 = blockIdx.y * BM;
    const int n0 = blockIdx.x * BN;

    if (tid < BN) { s_stat[0][tid] = 0.f; s_stat[1][tid] = 0.f; }
    if (tid < BM) s_invc[tid] = 1.f / fmaxf(g_counts[m0 + tid], 1.f);
    __syncthreads();

    #pragma unroll
    for (int i = 0; i < 16; i++) {
        const int task = i * 256 + tid;
        const int row = task >> 5, c8 = (task & 31) * 8;
        float f[8];
        *(float4*)&f[0] = *(const float4*)&g_segsum[(size_t)(m0 + row) * HID + c8];
        *(float4*)&f[4] = *(const float4*)&g_segsum[(size_t)(m0 + row) * HID + c8 + 4];
        const float ic = s_invc[row];
        #pragma unroll
        for (int j = 0; j < 8; j++) f[j] *= ic;
        *(uint4*)&sA[row][c8] = pack8(f);
    }
    #pragma unroll
    for (int i = 0; i < 8; i++) {
        const int task = i * 256 + tid;
        const int row = task >> 5, c8 = (task & 31) * 8;
        float f[8];
        *(float4*)&f[0] = *(const float4*)&W1[(size_t)(n0 + row) * HID + c8];
        *(float4*)&f[4] = *(const float4*)&W1[(size_t)(n0 + row) * HID + c8 + 4];
        *(uint4*)&sB[row][c8] = pack8(f);
    }
    __syncthreads();

    const int warp = tid >> 5, lane = tid & 31;
    const int wm0 = (warp >> 1) * 32;
    const int wn0 = (warp & 1) * 32;
    const int q = lane >> 3, r = lane & 7;

    float acc[2][4][4];
    #pragma unroll
    for (int i = 0; i < 2; i++)
        #pragma unroll
        for (int j = 0; j < 4; j++)
            #pragma unroll
            for (int k = 0; k < 4; k++) acc[i][j][k] = 0.f;

    #pragma unroll
    for (int kk = 0; kk < HID; kk += 16) {
        uint32_t ah[2][4], bh[2][4];
        #pragma unroll
        for (int mt = 0; mt < 2; mt++) {
            const int row = wm0 + mt * 16 + (q & 1) * 8 + r;
            const int col = kk + (q >> 1) * 8;
            ldsm4(ah[mt][0], ah[mt][1], ah[mt][2], ah[mt][3], &sA[row][col]);
        }
        #pragma unroll
        for (int p = 0; p < 2; p++) {
            const int row = wn0 + p * 16 + (q >> 1) * 8 + r;
            const int col = kk + (q & 1) * 8;
            ldsm4(bh[p][0], bh[p][1], bh[p][2], bh[p][3], &sB[row][col]);
        }
        #pragma unroll
        for (int mt = 0; mt < 2; mt++)
            #pragma unroll
            for (int nt = 0; nt < 4; nt++)
                mma16816h(acc[mt][nt], ah[mt][0], ah[mt][1], ah[mt][2], ah[mt][3],
                          bh[nt >> 1][(nt & 1) * 2], bh[nt >> 1][(nt & 1) * 2 + 1]);
    }

    float pre_g = 0.f, pre_b = 0.f, pre_w = 0.f;
    if (tid < BN) {
        pre_g = gamma[n0 + tid];
        pre_b = beta[n0 + tid];
        pre_w = W2[n0 + tid];
    }
    const float b2v = b2[0];

    #pragma unroll
    for (int nt = 0; nt < 4; nt++) {
        const int col = n0 + wn0 + nt * 8 + (lane & 3) * 2;
        const float bx = b1[col], by = b1[col + 1];
        float sx = 0.f, sy = 0.f, qx = 0.f, qy = 0.f;
        #pragma unroll
        for (int mt = 0; mt < 2; mt++) {
            acc[mt][nt][0] += bx; acc[mt][nt][1] += by;
            acc[mt][nt][2] += bx; acc[mt][nt][3] += by;
            sx += acc[mt][nt][0] + acc[mt][nt][2];
            sy += acc[mt][nt][1] + acc[mt][nt][3];
            qx = fmaf(acc[mt][nt][0], acc[mt][nt][0], qx);
            qx = fmaf(acc[mt][nt][2], acc[mt][nt][2], qx);
            qy = fmaf(acc[mt][nt][1], acc[mt][nt][1], qy);
            qy = fmaf(acc[mt][nt][3], acc[mt][nt][3], qy);
        }
        #pragma unroll
        for (int off = 16; off >= 4; off >>= 1) {
            sx += __shfl_down_sync(0xFFFFFFFFu, sx, off);
            sy += __shfl_down_sync(0xFFFFFFFFu, sy, off);
            qx += __shfl_down_sync(0xFFFFFFFFu, qx, off);
            qy += __shfl_down_sync(0xFFFFFFFFu, qy, off);
        }
        if (lane < 4) {
            const int c = wn0 + nt * 8 + lane * 2;
            atomicAdd(&s_stat[0][c], sx);
            atomicAdd(&s_stat[0][c + 1], sy);
            atomicAdd(&s_stat[1][c], qx);
            atomicAdd(&s_stat[1][c + 1], qy);
        }
    }
    __syncthreads();
    if (tid < BN) {
        atomicAdd(&g_sums[n0 + tid], s_stat[0][tid]);
        atomicAdd(&g_sumsq[n0 + tid], s_stat[1][tid]);
    }

    grid_sync(tid, &g_cnt1, &g_flag1);

    if (tid < BN) {
        const int c = n0 + tid;
        float mean = __ldcg(&g_sums[c]) * (1.f / BATCH);
        float var = fmaxf(__ldcg(&g_sumsq[c]) * (1.f / BATCH) - mean * mean, 0.f);
        float rstd = rsqrtf(var + BN_EPS);
        float sc = pre_g * rstd;
        s_sc[tid] = sc;
        s_sh[tid] = fmaf(-mean, sc, pre_b);
        s_w2[tid] = pre_w;
    }
    __syncthreads();

    {
        const int cl = wn0 + (lane & 3) * 2;
        float p[2][2];
        p[0][0] = p[0][1] = p[1][0] = p[1][1] = 0.f;
        #pragma unroll
        for (int nt = 0; nt < 4; nt++) {
            const int c0 = cl + nt * 8, c1 = c0 + 1;
            const float sc0 = s_sc[c0], sh0 = s_sh[c0], w20 = s_w2[c0];
            const float sc1 = s_sc[c1], sh1 = s_sh[c1], w21 = s_w2[c1];
            #pragma unroll
            for (int mt = 0; mt < 2; mt++) {
                float x;
                x = fmaxf(fmaf(acc[mt][nt][0], sc0, sh0), 0.f); p[mt][0] = fmaf(x, w20, p[mt][0]);
                x = fmaxf(fmaf(acc[mt][nt][1], sc1, sh1), 0.f); p[mt][0] = fmaf(x, w21, p[mt][0]);
                x = fmaxf(fmaf(acc[mt][nt][2], sc0, sh0), 0.f); p[mt][1] = fmaf(x, w20, p[mt][1]);
                x = fmaxf(fmaf(acc[mt][nt][3], sc1, sh1), 0.f); p[mt][1] = fmaf(x, w21, p[mt][1]);
            }
        }
        #pragma unroll
        for (int off = 2; off >= 1; off >>= 1) {
            #pragma unroll
            for (int mt = 0; mt < 2; mt++) {
                p[mt][0] += __shfl_down_sync(0xFFFFFFFFu, p[mt][0], off);
                p[mt][1] += __shfl_down_sync(0xFFFFFFFFu, p[mt][1], off);
            }
        }
        if ((lane & 3) == 0) {
            const int row0 = m0 + wm0 + (lane >> 2);
            #pragma unroll
            for (int mt = 0; mt < 2; mt++) {
                atomicAdd(&g_logit[row0 + mt * 16], p[mt][0]);
                atomicAdd(&g_logit[row0 + mt * 16 + 8], p[mt][1]);
            }
        }
    }

    __threadfence();
    __syncthreads();
    if (tid == 0) s_last = atomicAdd(&g_cnt_row[blockIdx.y], 1);
    __syncthreads();
    if (s_last != 3) return;

    {
        float l = 0.f;
        if (tid < BM) {
            const int row = m0 + tid;
            float logit = __ldcg(&g_logit[row]) + b2v;
            out[1 + row] = logit;
            float y = labels[row];
            l = fmaxf(logit, 0.f) - logit * y + log1pf(expf(-fabsf(logit)));
        }
        #pragma unroll
        for (int off = 16; off > 0; off >>= 1)
            l += __shfl_down_sync(0xFFFFFFFFu, l, off);
        if (lane == 0 && warp < 4) s_lred[warp] = l;
        __syncthreads();
        if (tid == 0) {
            float L = s_lred[0] + s_lred[1] + s_lred[2] + s_lred[3];
            atomicAdd(&g_loss, L);
            __threadfence();
            if (atomicAdd(&g_done, 1) == 31) {
                out[0] = atomicAdd(&g_loss, 0.f) * (1.f / BATCH);
            }
        }
    }
}

// -------- launch: maximal two-stream overlap --------------------------------
// stream0: prep0 -> gather0 ............ -> (wait gather1) fused
// stream1: (wait prep0) prep1 -> gather1 -> record
extern "C" void kernel_launch(void* const* d_in, const int* in_sizes, int n_in,
                              void* d_out, int out_size) {
    const int*   tok    = (const int*)d_in[0];
    const int*   seg    = (const int*)d_in[1];
    const float* labels = (const float*)d_in[2];
    const float* emb    = (const float*)d_in[3];
    const float* W1     = (const float*)d_in[4];
    const float* b1     = (const float*)d_in[5];
    const float* gamma  = (const float*)d_in[6];
    const float* beta   = (const float*)d_in[7];
    const float* W2     = (const float*)d_in[8];
    const float* b2     = (const float*)d_in[9];
    float* out = (float*)d_out;

    static cudaStream_t s1 = nullptr;
    static cudaEvent_t ev_fork = nullptr, ev_join = nullptr;
    if (s1 == nullptr) {   // first call is the uncaptured correctness run
        cudaStreamCreateWithFlags(&s1, cudaStreamNonBlocking);
        cudaEventCreateWithFlags(&ev_fork, cudaEventDisableTiming);
        cudaEventCreateWithFlags(&ev_join, cudaEventDisableTiming);
        cudaFuncSetAttribute(k_fused, cudaFuncAttributeMaxDynamicSharedMemorySize,
                             DYN_SMEM);
    }

    // prep half 0 (+ all zero-init + dtype detect) on stream 0
    k_prep_half<<<6250 + 1026, 256>>>(emb, tok, 0);
    cudaEventRecord(ev_fork, 0);

    // stream 1: prep half 1 then gather pass 1
    cudaStreamWaitEvent(s1, ev_fork, 0);
    k_prep_half<<<6250, 256, 0, s1>>>(emb, tok, 1);
    k_gather<<<N_TOK / (TOK_PER_WARP * GATHER_WARPS), GATHER_WARPS * 32, 0, s1>>>(tok, seg, 1);
    cudaEventRecord(ev_join, s1);

    // stream 0: gather pass 0 (needs only half 0), then fused after join
    k_gather<<<N_TOK / (TOK_PER_WARP * GATHER_WARPS), GATHER_WARPS * 32>>>(tok, seg, 0);
    cudaStreamWaitEvent(0, ev_join, 0);
    k_fused<<<dim3(HID / BN, BATCH / BM), 256, DYN_SMEM>>>(W1, b1, gamma, beta, W2,
                                                           b2, labels, out);
}

// round 17
// speedup vs baseline: 1.3456x; 1.0927x over previous
#include <cuda_runtime.h>
#include <cuda_fp16.h>
#include <cuda_bf16.h>
#include <cstdint>

#define VOCAB   100000
#define N_TOK   819200
#define BATCH   4096
#define HID     256
#define BN_EPS  1e-5f
#define NBLK    128        // fused grid size (4 x 32); single wave (<=148 SMs)

// ---------------- device scratch (no allocations allowed) ----------------
__device__ __align__(16) __half g_emb_h[(size_t)VOCAB * HID];  // 51.2 MB fp16 table
__device__ __align__(16) float g_segsum[BATCH * HID];          // 4 MB
__device__ __align__(16) float g_counts[BATCH];
__device__ __align__(16) float g_sums[HID];
__device__ __align__(16) float g_sumsq[HID];
__device__ __align__(16) float g_logit[BATCH];
__device__ float g_loss;
__device__ int   g_nz;     // nonzero odd words => int32 ids
__device__ int   g_done;   // ticket over the 32 row-group finalizers
__device__ int   g_cnt1;
__device__ volatile int g_flag1;
__device__ int   g_cnt_row[32];          // per-by arrival counters

__device__ __forceinline__ uint64_t mk_evict_last_policy() {
    uint64_t policy;
    asm volatile("createpolicy.fractional.L2::evict_last.b64 %0, 1.0;"
                 : "=l"(policy));
    return policy;
}

// ---------------- prep: fp32->fp16 table convert + zero state + detect ----
// Table stores carry an evict_last policy so the fp16 table stays L2-resident
// and its DRAM write-back defers into the gather window (DRAM idle there).
__global__ void __launch_bounds__(256)
k_prep(const float* __restrict__ emb, const int* __restrict__ tok) {
    const int bid = blockIdx.x, tid = threadIdx.x;
    size_t idx = ((size_t)bid * 256 + tid) * 8;
    const float4* src = (const float4*)(emb + idx);
    float4 v0 = __ldcs(src);        // evict-first reads: don't displace the table
    float4 v1 = __ldcs(src + 1);
    uint4 pack;
    __half2 h;
    h = __floats2half2_rn(v0.x, v0.y); pack.x = *(uint32_t*)&h;
    h = __floats2half2_rn(v0.z, v0.w); pack.y = *(uint32_t*)&h;
    h = __floats2half2_rn(v1.x, v1.y); pack.z = *(uint32_t*)&h;
    h = __floats2half2_rn(v1.z, v1.w); pack.w = *(uint32_t*)&h;
    uint64_t policy = mk_evict_last_policy();
    asm volatile("st.global.L2::cache_hint.v4.u32 [%0], {%1,%2,%3,%4}, %5;"
                 :: "l"(g_emb_h + idx), "r"(pack.x), "r"(pack.y),
                    "r"(pack.z), "r"(pack.w), "l"(policy) : "memory");

    if (bid < 1024) {
        *(float4*)&g_segsum[bid * 1024 + tid * 4] = make_float4(0.f, 0.f, 0.f, 0.f);
    } else if (bid == 1024) {
        float4 z = make_float4(0.f, 0.f, 0.f, 0.f);
        #pragma unroll
        for (int i = 0; i < 4; i++) {
            *(float4*)&g_counts[tid * 16 + i * 4] = z;
            *(float4*)&g_logit[tid * 16 + i * 4] = z;
        }
        g_sums[tid] = 0.f;
        g_sumsq[tid] = 0.f;
        if (tid < 32) g_cnt_row[tid] = 0;
        if (tid == 0) { g_loss = 0.f; g_done = 0; g_cnt1 = 0; g_flag1 = 0; }
    } else if (bid == 1025 && tid < 64) {
        if (tok[2 * tid + 1] != 0) atomicOr(&g_nz, 1);
    }
}

// ---------------- gather + segment sum (fp16 table, fp32 accumulate) ------
#define TOK_PER_WARP 64
#define GATHER_WARPS 8

__device__ __forceinline__ void flush_run(int seg, const float* a, int runlen, int lane) {
    float* dst = g_segsum + (size_t)seg * HID + lane * 8;
    asm volatile("red.global.add.v4.f32 [%0], {%1,%2,%3,%4};"
                 :: "l"(dst), "f"(a[0]), "f"(a[1]), "f"(a[2]), "f"(a[3]) : "memory");
    asm volatile("red.global.add.v4.f32 [%0], {%1,%2,%3,%4};"
                 :: "l"(dst + 4), "f"(a[4]), "f"(a[5]), "f"(a[6]), "f"(a[7]) : "memory");
    if (lane == 0) atomicAdd(&g_counts[seg], (float)runlen);
}

// evict_last table load: policy register + cache_hint form (legal at .v4.u32)
__device__ __forceinline__ uint4 ld_tbl(const __half* p, uint64_t policy) {
    uint4 v;
    asm volatile("ld.global.nc.L2::cache_hint.v4.u32 {%0,%1,%2,%3}, [%4], %5;"
                 : "=r"(v.x), "=r"(v.y), "=r"(v.z), "=r"(v.w)
                 : "l"(p), "l"(policy));
    return v;
}

__global__ void __launch_bounds__(GATHER_WARPS * 32)
k_gather(const int* __restrict__ tok, const int* __restrict__ seg) {
    const uint64_t policy = mk_evict_last_policy();

    const int stride = g_nz ? 1 : 2;
    const int lane = threadIdx.x & 31;
    const int warp_id = blockIdx.x * GATHER_WARPS + (threadIdx.x >> 5);
    const int t0 = warp_id * TOK_PER_WARP;

    int idp[2], sgp[2];
    idp[0] = tok[(size_t)(t0 + lane) * stride];
    idp[1] = tok[(size_t)(t0 + 32 + lane) * stride];
    sgp[0] = seg[(size_t)(t0 + lane) * stride];
    sgp[1] = seg[(size_t)(t0 + 32 + lane) * stride];

    float a[8];
    #pragma unroll
    for (int i = 0; i < 8; i++) a[i] = 0.f;
    int cur = __shfl_sync(0xFFFFFFFFu, sgp[0], 0);
    int runlen = 0;

    const size_t lane_off = lane * 8;

    #pragma unroll
    for (int hf = 0; hf < 2; ++hf) {
        #pragma unroll 8
        for (int i = 0; i < 32; ++i) {
            int s  = __shfl_sync(0xFFFFFFFFu, sgp[hf], i);
            int id = __shfl_sync(0xFFFFFFFFu, idp[hf], i);
            if (s != cur) {
                flush_run(cur, a, runlen, lane);
                #pragma unroll
                for (int j = 0; j < 8; j++) a[j] = 0.f;
                runlen = 0;
                cur = s;
            }
            uint4 v = ld_tbl(g_emb_h + (size_t)id * HID + lane_off, policy);
            const __half2* hp = (const __half2*)&v;
            float2 f;
            f = __half22float2(hp[0]); a[0] += f.x; a[1] += f.y;
            f = __half22float2(hp[1]); a[2] += f.x; a[3] += f.y;
            f = __half22float2(hp[2]); a[4] += f.x; a[5] += f.y;
            f = __half22float2(hp[3]); a[6] += f.x; a[7] += f.y;
            ++runlen;
        }
    }
    flush_run(cur, a, runlen, lane);
}

// ---------------- fused GEMM + BN + ReLU + W2 + BCE (persistent) ----------
#define BM 128
#define BN 64
#define APAD 264   // halves per row; 528B pitch => ldmatrix conflict-free
#define SA_HALVES (BM * APAD)
#define SB_HALVES (BN * APAD)
#define DYN_SMEM ((SA_HALVES + SB_HALVES) * 2)

__device__ __forceinline__ void ldsm4(uint32_t& r0, uint32_t& r1, uint32_t& r2,
                                      uint32_t& r3, const void* p) {
    uint32_t addr = (uint32_t)__cvta_generic_to_shared(p);
    asm volatile("ldmatrix.sync.aligned.m8n8.x4.shared.b16 {%0,%1,%2,%3}, [%4];"
                 : "=r"(r0), "=r"(r1), "=r"(r2), "=r"(r3) : "r"(addr));
}

__device__ __forceinline__ void mma16816h(float* c, uint32_t a0, uint32_t a1,
                                          uint32_t a2, uint32_t a3,
                                          uint32_t b0, uint32_t b1) {
    asm volatile(
        "mma.sync.aligned.m16n8k16.row.col.f32.f16.f16.f32 "
        "{%0,%1,%2,%3}, {%4,%5,%6,%7}, {%8,%9}, {%0,%1,%2,%3};"
        : "+f"(c[0]), "+f"(c[1]), "+f"(c[2]), "+f"(c[3])
        : "r"(a0), "r"(a1), "r"(a2), "r"(a3), "r"(b0), "r"(b1));
}

// R7-proven single-wave full grid barrier
__device__ __forceinline__ void grid_sync(int tid, int* cnt, volatile int* flag) {
    __syncthreads();
    if (tid == 0) {
        __threadfence();
        if (atomicAdd(cnt, 1) == NBLK - 1) {
            *flag = 1;
        } else {
            while (*flag == 0) __nanosleep(64);
        }
    }
    __syncthreads();
}

__device__ __forceinline__ uint4 pack8(const float* f) {
    uint4 o;
    __half2 h;
    h = __floats2half2_rn(f[0], f[1]); o.x = *(uint32_t*)&h;
    h = __floats2half2_rn(f[2], f[3]); o.y = *(uint32_t*)&h;
    h = __floats2half2_rn(f[4], f[5]); o.z = *(uint32_t*)&h;
    h = __floats2half2_rn(f[6], f[7]); o.w = *(uint32_t*)&h;
    return o;
}

__global__ void __launch_bounds__(256)
k_fused(const float* __restrict__ W1, const float* __restrict__ b1,
        const float* __restrict__ gamma, const float* __restrict__ beta,
        const float* __restrict__ W2, const float* __restrict__ b2,
        const float* __restrict__ labels, float* __restrict__ out) {
    extern __shared__ __align__(16) char dynsmem[];
    __half (*sA)[APAD] = (__half (*)[APAD])dynsmem;
    __half (*sB)[APAD] = (__half (*)[APAD])(dynsmem + SA_HALVES * 2);

    __shared__ float s_invc[BM];
    __shared__ float s_stat[2][BN];
    __shared__ float s_sc[BN], s_sh[BN], s_w2[BN];
    __shared__ int s_last;
    __shared__ float s_lred[4];

    const int tid = threadIdx.x;
    const int m0 = blockIdx.y * BM;
    const int n0 = blockIdx.x * BN;

    if (tid < BN) { s_stat[0][tid] = 0.f; s_stat[1][tid] = 0.f; }
    if (tid < BM) s_invc[tid] = 1.f / fmaxf(g_counts[m0 + tid], 1.f);
    __syncthreads();

    #pragma unroll
    for (int i = 0; i < 16; i++) {
        const int task = i * 256 + tid;
        const int row = task >> 5, c8 = (task & 31) * 8;
        float f[8];
        *(float4*)&f[0] = *(const float4*)&g_segsum[(size_t)(m0 + row) * HID + c8];
        *(float4*)&f[4] = *(const float4*)&g_segsum[(size_t)(m0 + row) * HID + c8 + 4];
        const float ic = s_invc[row];
        #pragma unroll
        for (int j = 0; j < 8; j++) f[j] *= ic;
        *(uint4*)&sA[row][c8] = pack8(f);
    }
    #pragma unroll
    for (int i = 0; i < 8; i++) {
        const int task = i * 256 + tid;
        const int row = task >> 5, c8 = (task & 31) * 8;
        float f[8];
        *(float4*)&f[0] = *(const float4*)&W1[(size_t)(n0 + row) * HID + c8];
        *(float4*)&f[4] = *(const float4*)&W1[(size_t)(n0 + row) * HID + c8 + 4];
        *(uint4*)&sB[row][c8] = pack8(f);
    }
    __syncthreads();

    const int warp = tid >> 5, lane = tid & 31;
    const int wm0 = (warp >> 1) * 32;
    const int wn0 = (warp & 1) * 32;
    const int q = lane >> 3, r = lane & 7;

    float acc[2][4][4];
    #pragma unroll
    for (int i = 0; i < 2; i++)
        #pragma unroll
        for (int j = 0; j < 4; j++)
            #pragma unroll
            for (int k = 0; k < 4; k++) acc[i][j][k] = 0.f;

    #pragma unroll
    for (int kk = 0; kk < HID; kk += 16) {
        uint32_t ah[2][4], bh[2][4];
        #pragma unroll
        for (int mt = 0; mt < 2; mt++) {
            const int row = wm0 + mt * 16 + (q & 1) * 8 + r;
            const int col = kk + (q >> 1) * 8;
            ldsm4(ah[mt][0], ah[mt][1], ah[mt][2], ah[mt][3], &sA[row][col]);
        }
        #pragma unroll
        for (int p = 0; p < 2; p++) {
            const int row = wn0 + p * 16 + (q >> 1) * 8 + r;
            const int col = kk + (q & 1) * 8;
            ldsm4(bh[p][0], bh[p][1], bh[p][2], bh[p][3], &sB[row][col]);
        }
        #pragma unroll
        for (int mt = 0; mt < 2; mt++)
            #pragma unroll
            for (int nt = 0; nt < 4; nt++)
                mma16816h(acc[mt][nt], ah[mt][0], ah[mt][1], ah[mt][2], ah[mt][3],
                          bh[nt >> 1][(nt & 1) * 2], bh[nt >> 1][(nt & 1) * 2 + 1]);
    }

    float pre_g = 0.f, pre_b = 0.f, pre_w = 0.f;
    if (tid < BN) {
        pre_g = gamma[n0 + tid];
        pre_b = beta[n0 + tid];
        pre_w = W2[n0 + tid];
    }
    const float b2v = b2[0];

    #pragma unroll
    for (int nt = 0; nt < 4; nt++) {
        const int col = n0 + wn0 + nt * 8 + (lane & 3) * 2;
        const float bx = b1[col], by = b1[col + 1];
        float sx = 0.f, sy = 0.f, qx = 0.f, qy = 0.f;
        #pragma unroll
        for (int mt = 0; mt < 2; mt++) {
            acc[mt][nt][0] += bx; acc[mt][nt][1] += by;
            acc[mt][nt][2] += bx; acc[mt][nt][3] += by;
            sx += acc[mt][nt][0] + acc[mt][nt][2];
            sy += acc[mt][nt][1] + acc[mt][nt][3];
            qx = fmaf(acc[mt][nt][0], acc[mt][nt][0], qx);
            qx = fmaf(acc[mt][nt][2], acc[mt][nt][2], qx);
            qy = fmaf(acc[mt][nt][1], acc[mt][nt][1], qy);
            qy = fmaf(acc[mt][nt][3], acc[mt][nt][3], qy);
        }
        #pragma unroll
        for (int off = 16; off >= 4; off >>= 1) {
            sx += __shfl_down_sync(0xFFFFFFFFu, sx, off);
            sy += __shfl_down_sync(0xFFFFFFFFu, sy, off);
            qx += __shfl_down_sync(0xFFFFFFFFu, qx, off);
            qy += __shfl_down_sync(0xFFFFFFFFu, qy, off);
        }
        if (lane < 4) {
            const int c = wn0 + nt * 8 + lane * 2;
            atomicAdd(&s_stat[0][c], sx);
            atomicAdd(&s_stat[0][c + 1], sy);
            atomicAdd(&s_stat[1][c], qx);
            atomicAdd(&s_stat[1][c + 1], qy);
        }
    }
    __syncthreads();
    if (tid < BN) {
        atomicAdd(&g_sums[n0 + tid], s_stat[0][tid]);
        atomicAdd(&g_sumsq[n0 + tid], s_stat[1][tid]);
    }

    grid_sync(tid, &g_cnt1, &g_flag1);

    if (tid < BN) {
        const int c = n0 + tid;
        float mean = __ldcg(&g_sums[c]) * (1.f / BATCH);
        float var = fmaxf(__ldcg(&g_sumsq[c]) * (1.f / BATCH) - mean * mean, 0.f);
        float rstd = rsqrtf(var + BN_EPS);
        float sc = pre_g * rstd;
        s_sc[tid] = sc;
        s_sh[tid] = fmaf(-mean, sc, pre_b);
        s_w2[tid] = pre_w;
    }
    __syncthreads();

    {
        const int cl = wn0 + (lane & 3) * 2;
        float p[2][2];
        p[0][0] = p[0][1] = p[1][0] = p[1][1] = 0.f;
        #pragma unroll
        for (int nt = 0; nt < 4; nt++) {
            const int c0 = cl + nt * 8, c1 = c0 + 1;
            const float sc0 = s_sc[c0], sh0 = s_sh[c0], w20 = s_w2[c0];
            const float sc1 = s_sc[c1], sh1 = s_sh[c1], w21 = s_w2[c1];
            #pragma unroll
            for (int mt = 0; mt < 2; mt++) {
                float x;
                x = fmaxf(fmaf(acc[mt][nt][0], sc0, sh0), 0.f); p[mt][0] = fmaf(x, w20, p[mt][0]);
                x = fmaxf(fmaf(acc[mt][nt][1], sc1, sh1), 0.f); p[mt][0] = fmaf(x, w21, p[mt][0]);
                x = fmaxf(fmaf(acc[mt][nt][2], sc0, sh0), 0.f); p[mt][1] = fmaf(x, w20, p[mt][1]);
                x = fmaxf(fmaf(acc[mt][nt][3], sc1, sh1), 0.f); p[mt][1] = fmaf(x, w21, p[mt][1]);
            }
        }
        #pragma unroll
        for (int off = 2; off >= 1; off >>= 1) {
            #pragma unroll
            for (int mt = 0; mt < 2; mt++) {
                p[mt][0] += __shfl_down_sync(0xFFFFFFFFu, p[mt][0], off);
                p[mt][1] += __shfl_down_sync(0xFFFFFFFFu, p[mt][1], off);
            }
        }
        if ((lane & 3) == 0) {
            const int row0 = m0 + wm0 + (lane >> 2);
            #pragma unroll
            for (int mt = 0; mt < 2; mt++) {
                atomicAdd(&g_logit[row0 + mt * 16], p[mt][0]);
                atomicAdd(&g_logit[row0 + mt * 16 + 8], p[mt][1]);
            }
        }
    }

    __threadfence();
    __syncthreads();
    if (tid == 0) s_last = atomicAdd(&g_cnt_row[blockIdx.y], 1);
    __syncthreads();
    if (s_last != 3) return;

    {
        float l = 0.f;
        if (tid < BM) {
            const int row = m0 + tid;
            float logit = __ldcg(&g_logit[row]) + b2v;
            out[1 + row] = logit;
            float y = labels[row];
            l = fmaxf(logit, 0.f) - logit * y + log1pf(expf(-fabsf(logit)));
        }
        #pragma unroll
        for (int off = 16; off > 0; off >>= 1)
            l += __shfl_down_sync(0xFFFFFFFFu, l, off);
        if (lane == 0 && warp < 4) s_lred[warp] = l;
        __syncthreads();
        if (tid == 0) {
            float L = s_lred[0] + s_lred[1] + s_lred[2] + s_lred[3];
            atomicAdd(&g_loss, L);
            __threadfence();
            if (atomicAdd(&g_done, 1) == 31) {
                out[0] = atomicAdd(&g_loss, 0.f) * (1.f / BATCH);
            }
        }
    }
}

// ---------------- launch ----------------
extern "C" void kernel_launch(void* const* d_in, const int* in_sizes, int n_in,
                              void* d_out, int out_size) {
    const int*   tok    = (const int*)d_in[0];
    const int*   seg    = (const int*)d_in[1];
    const float* labels = (const float*)d_in[2];
    const float* emb    = (const float*)d_in[3];
    const float* W1     = (const float*)d_in[4];
    const float* b1     = (const float*)d_in[5];
    const float* gamma  = (const float*)d_in[6];
    const float* beta   = (const float*)d_in[7];
    const float* W2     = (const float*)d_in[8];
    const float* b2     = (const float*)d_in[9];
    float* out = (float*)d_out;

    static bool attr_set = false;
    if (!attr_set) {
        cudaFuncSetAttribute(k_fused, cudaFuncAttributeMaxDynamicSharedMemorySize,
                             DYN_SMEM);
        attr_set = true;
    }

    k_prep<<<(VOCAB * HID) / (256 * 8), 256>>>(emb, tok);
    k_gather<<<N_TOK / (TOK_PER_WARP * GATHER_WARPS), GATHER_WARPS * 32>>>(tok, seg);
    k_fused<<<dim3(HID / BN, BATCH / BM), 256, DYN_SMEM>>>(W1, b1, gamma, beta, W2,
                                                           b2, labels, out);
}